// round 15
// baseline (speedup 1.0000x reference)
#include <cuda_runtime.h>
#include <cuda_bf16.h>
#include <cstdint>

// ---------------------------------------------------------------------------
// Problem shapes (fixed)
// ---------------------------------------------------------------------------
#define B_  8
#define T_  2048
#define X_  64
#define H_  256
#define C_  32
#define TM1 2047
#define LOG2PI 1.8378770664093453

typedef unsigned long long ull;

// ---------------------------------------------------------------------------
// Scratch (device globals — no allocation allowed)
// ---------------------------------------------------------------------------
__device__ float  g_gi   [3 * B_ * T_ * H_];      // 3 gate planes [g][B,T,H]
__device__ float  g_hseq [B_ * T_ * H_];
__device__ float  g_ctx  [B_ * TM1 * (H_ + 1)];
__device__ float  g_hs1  [B_ * TM1 * H_];
__device__ float  g_hs2  [B_ * TM1 * H_];
__device__ float  g_par  [B_ * TM1 * 3 * C_];
__device__ float  g_m0   [B_ * C_];
__device__ float  g_s0   [B_ * C_];
__device__ double g_part [B_ * C_];

// ---------------------------------------------------------------------------
// Helpers
// ---------------------------------------------------------------------------
__device__ __forceinline__ float softplusf_(float x) {
    return fmaxf(x, 0.f) + log1pf(expf(-fabsf(x)));
}
__device__ __forceinline__ float siluf_(float x) { return x / (1.f + expf(-x)); }
__device__ __forceinline__ float fast_sigmoid(float x) {
    return __fdividef(1.f, 1.f + __expf(-x));
}
__device__ __forceinline__ float fast_tanh(float x) {
    float xc = fminf(fmaxf(x, -15.f), 15.f);
    float e = __expf(2.f * xc);
    return __fdividef(e - 1.f, e + 1.f);
}

__device__ __forceinline__ float2 unpack_f32x2(ull v) {
    float2 r;
    asm("mov.b64 {%0,%1}, %2;" : "=f"(r.x), "=f"(r.y) : "l"(v));
    return r;
}
__device__ __forceinline__ ull pack2(float x, float y) {
    ull v;
    asm("mov.b64 %0, {%1,%2};" : "=l"(v) : "f"(x), "f"(y));
    return v;
}
__device__ __forceinline__ void fma_f32x2(ull& acc, ull a, ull b) {
    asm("fma.rn.f32x2 %0, %1, %2, %0;" : "+l"(acc) : "l"(a), "l"(b));
}
__device__ __forceinline__ void cluster_sync_() {
    asm volatile("barrier.cluster.arrive.aligned;" ::: "memory");
    asm volatile("barrier.cluster.wait.aligned;" ::: "memory");
}
__device__ __forceinline__ uint32_t smem_u32(const void* p) {
    return (uint32_t)__cvta_generic_to_shared(p);
}
__device__ __forceinline__ uint32_t mapa_u32(uint32_t laddr, unsigned rank) {
    uint32_t raddr;
    asm volatile("mapa.shared::cluster.u32 %0, %1, %2;" : "=r"(raddr) : "r"(laddr), "r"(rank));
    return raddr;
}
__device__ __forceinline__ void st_cluster_v4(uint32_t raddr, float4 v) {
    asm volatile("st.shared::cluster.v4.f32 [%0], {%1,%2,%3,%4};"
                 :: "r"(raddr), "f"(v.x), "f"(v.y), "f"(v.z), "f"(v.w) : "memory");
}
__device__ __forceinline__ void mbar_init(uint32_t addr, uint32_t count) {
    asm volatile("mbarrier.init.shared.b64 [%0], %1;" :: "r"(addr), "r"(count) : "memory");
}
__device__ __forceinline__ void mbar_arrive_remote(uint32_t raddr) {
    asm volatile("mbarrier.arrive.release.cluster.shared::cluster.b64 _, [%0];"
                 :: "r"(raddr) : "memory");
}
__device__ __forceinline__ void mbar_wait(uint32_t addr, uint32_t parity) {
    asm volatile(
        "{\n\t"
        ".reg .pred P;\n\t"
        "WL_%=:\n\t"
        "mbarrier.try_wait.parity.acquire.cluster.shared::cta.b64 P, [%0], %1, 0x989680;\n\t"
        "@!P bra WL_%=;\n\t"
        "}" :: "r"(addr), "r"(parity) : "memory");
}

// ---------------------------------------------------------------------------
// GEMM: C[M,N] = act( A[M,K] * B[N,K]^T + bias[N] )  (unchanged)
// ---------------------------------------------------------------------------
template <int ACT>
__global__ __launch_bounds__(256)
void gemm_tn(const float* __restrict__ A, const float* __restrict__ B,
             const float* __restrict__ bias, float* __restrict__ C,
             int M, int N, int K)
{
    __shared__ float As[16][132];
    __shared__ float Bs[16][68];
    const int tid = threadIdx.x;
    const int tx = tid & 15, ty = tid >> 4;
    const int bm = blockIdx.y * 128, bn = blockIdx.x * 64;

    ull acc[4][4];
#pragma unroll
    for (int i = 0; i < 4; i++)
#pragma unroll
        for (int j = 0; j < 4; j++) acc[i][j] = 0ULL;

    for (int k0 = 0; k0 < K; k0 += 16) {
#pragma unroll
        for (int i = 0; i < 8; i++) {
            int e = tid + i * 256;
            int r = e >> 4, c = e & 15;
            int ga = bm + r, gc = k0 + c;
            float v = (ga < M && gc < K) ? A[(size_t)ga * K + gc] : 0.f;
            As[c][(r & 15) * 8 + (r >> 4)] = v;
        }
#pragma unroll
        for (int i = 0; i < 4; i++) {
            int e = tid + i * 256;
            int r = e >> 4, c = e & 15;
            int gb = bn + r, gc = k0 + c;
            Bs[c][r] = (gb < N && gc < K) ? B[(size_t)gb * K + gc] : 0.f;
        }
        __syncthreads();
#pragma unroll
        for (int kk = 0; kk < 16; kk++) {
            float4 a0 = *(const float4*)&As[kk][ty * 8];
            float4 a1 = *(const float4*)&As[kk][ty * 8 + 4];
            float4 bq = *(const float4*)&Bs[kk][tx * 4];
            ull ap[4] = { pack2(a0.x, a0.y), pack2(a0.z, a0.w),
                          pack2(a1.x, a1.y), pack2(a1.z, a1.w) };
            ull bd[4] = { pack2(bq.x, bq.x), pack2(bq.y, bq.y),
                          pack2(bq.z, bq.z), pack2(bq.w, bq.w) };
#pragma unroll
            for (int P = 0; P < 4; P++)
#pragma unroll
                for (int j = 0; j < 4; j++)
                    fma_f32x2(acc[P][j], ap[P], bd[j]);
        }
        __syncthreads();
    }

#pragma unroll
    for (int P = 0; P < 4; P++) {
        float lo[4], hi[4];
#pragma unroll
        for (int j = 0; j < 4; j++) {
            float2 u = unpack_f32x2(acc[P][j]);
            lo[j] = u.x; hi[j] = u.y;
        }
#pragma unroll
        for (int half = 0; half < 2; half++) {
            int m = bm + ty + 32 * P + 16 * half;
            if (m >= M) continue;
            float* vv = half ? hi : lo;
            float* dst = C + (size_t)m * N;
#pragma unroll
            for (int j = 0; j < 4; j++) {
                int n = bn + tx * 4 + j;
                if (n >= N) continue;
                float v = vv[j] + bias[n];
                if (ACT == 1) v = siluf_(v);
                dst[n] = v;
            }
        }
    }
}

// ---------------------------------------------------------------------------
// GRU scan — reduce-scatter (R13) + 2-batch interleave. 4 clusters x 8 CTAs.
// Each cluster advances batches (2c, 2c+1) in lockstep per time index k:
//   sync -> A0 B0 -> A1 B1 -> (warp0: wait0 C0 -> wait1 C1)
// so each batch's fabric round-trip hides behind the other batch's phases.
// W column-slice registers are SHARED between the batches (same weights).
// Phase A (all warps): 48 f32x2 FMA partial dots from local hloc[bb][P].
// Phase B (warp w, autonomous): STS partials -> syncwarp -> lanes 0-23
//   copy 384B to peer w's accb[bb][P][rank] -> syncwarp -> lane0 arrive
//   (8 arrivals per barrier).
// Phase C (warp 0): wait -> sum 8 sources -> gates -> hloc[bb][P^1] +
//   coalesced hseq store + gi prefetch.
// Anti-dependency safety per batch identical to R13 (the shared
// __syncthreads is a superset of the per-batch ordering).
// ---------------------------------------------------------------------------
__global__ void __cluster_dims__(8, 1, 1) __launch_bounds__(256, 1)
gru_kernel(const float* __restrict__ gi, const float* __restrict__ Whh,
           const float* __restrict__ bhh, float* __restrict__ hseq)
{
    __shared__ __align__(16) float hloc[2][2][32];        // [batch][buf]
    __shared__ __align__(16) float accb[2][2][8][96];     // [batch][buf][src][96]
    __shared__ __align__(16) float stage[2][8][96];       // [batch][warp]
    __shared__ __align__(8) ull mbar[2][2];               // [batch][buf]
    const int tid  = threadIdx.x;
    const int w    = tid >> 5;
    const int lane = tid & 31;
    const unsigned rank = (unsigned)(blockIdx.x & 7);
    const int cp   = blockIdx.x >> 3;                     // cluster pair 0..3

    // W column-slice: rows g*H + tid, cols [32*rank, 32*rank+32)
    ull Wr[16], Wz[16], Wn[16];
    {
        const ull* wr = (const ull*)(Whh + ((size_t)(0 * H_ + tid)) * H_ + 32 * rank);
        const ull* wz = (const ull*)(Whh + ((size_t)(1 * H_ + tid)) * H_ + 32 * rank);
        const ull* wn = (const ull*)(Whh + ((size_t)(2 * H_ + tid)) * H_ + 32 * rank);
#pragma unroll
        for (int x = 0; x < 16; x++) { Wr[x] = wr[x]; Wz[x] = wz[x]; Wn[x] = wn[x]; }
    }
    const int J = (int)rank * 32 + lane;      // warp0's output index
    const float bhr = bhh[0 * H_ + J];
    const float bhz = bhh[1 * H_ + J];
    const float bhn = bhh[2 * H_ + J];

    const int b0 = 2 * cp, b1 = 2 * cp + 1;
    const float* g_r0 = gi + 0 * (size_t)B_ * T_ * H_ + (size_t)b0 * T_ * H_;
    const float* g_z0 = gi + 1 * (size_t)B_ * T_ * H_ + (size_t)b0 * T_ * H_;
    const float* g_n0 = gi + 2 * (size_t)B_ * T_ * H_ + (size_t)b0 * T_ * H_;
    const float* g_r1 = gi + 0 * (size_t)B_ * T_ * H_ + (size_t)b1 * T_ * H_;
    const float* g_z1 = gi + 1 * (size_t)B_ * T_ * H_ + (size_t)b1 * T_ * H_;
    const float* g_n1 = gi + 2 * (size_t)B_ * T_ * H_ + (size_t)b1 * T_ * H_;
    float gr0 = g_r0[J], gz0 = g_z0[J], gn0 = g_n0[J];
    float gr1 = g_r1[J], gz1 = g_z1[J], gn1 = g_n1[J];
    float* hout0 = hseq + (size_t)b0 * T_ * H_ + rank * 32 + lane;
    float* hout1 = hseq + (size_t)b1 * T_ * H_ + rank * 32 + lane;

    if (tid < 4) mbar_init(smem_u32(&mbar[tid >> 1][tid & 1]), 8);
    if (tid < 32) { hloc[0][0][tid] = 0.f; hloc[1][0][tid] = 0.f; }
    __syncthreads();
    cluster_sync_();    // barrier inits + zeros visible before remote traffic

    // Warp w delivers into peer w's accb[bb][P][rank] block.
    const uint32_t da00 = mapa_u32(smem_u32(&accb[0][0][rank][0]), (unsigned)w);
    const uint32_t da01 = mapa_u32(smem_u32(&accb[0][1][rank][0]), (unsigned)w);
    const uint32_t da10 = mapa_u32(smem_u32(&accb[1][0][rank][0]), (unsigned)w);
    const uint32_t da11 = mapa_u32(smem_u32(&accb[1][1][rank][0]), (unsigned)w);
    const uint32_t db00 = mapa_u32(smem_u32(&mbar[0][0]), (unsigned)w);
    const uint32_t db01 = mapa_u32(smem_u32(&mbar[0][1]), (unsigned)w);
    const uint32_t db10 = mapa_u32(smem_u32(&mbar[1][0]), (unsigned)w);
    const uint32_t db11 = mapa_u32(smem_u32(&mbar[1][1]), (unsigned)w);
    const uint32_t bl00 = smem_u32(&mbar[0][0]);
    const uint32_t bl01 = smem_u32(&mbar[0][1]);
    const uint32_t bl10 = smem_u32(&mbar[1][0]);
    const uint32_t bl11 = smem_u32(&mbar[1][1]);
    uint32_t ph00 = 0, ph01 = 0, ph10 = 0, ph11 = 0;

// Phase A+B for batch bb at buffer P (compile-time constants).
#define GRU_AB(bb, P, DA, DB)                                                   \
    {                                                                           \
        const ull* hp = (const ull*)hloc[bb][P];                                \
        ull ar = 0ULL, az = 0ULL, an = 0ULL;                                    \
        _Pragma("unroll")                                                       \
        for (int x = 0; x < 16; x++) {                                          \
            ull h2 = hp[x];                                                     \
            fma_f32x2(ar, Wr[x], h2);                                           \
            fma_f32x2(az, Wz[x], h2);                                           \
            fma_f32x2(an, Wn[x], h2);                                           \
        }                                                                       \
        float2 u;                                                               \
        u = unpack_f32x2(ar); float pr = u.x + u.y;                             \
        u = unpack_f32x2(az); float pz = u.x + u.y;                             \
        u = unpack_f32x2(an); float pn = u.x + u.y;                             \
        stage[bb][w][lane]      = pr;                                           \
        stage[bb][w][32 + lane] = pz;                                           \
        stage[bb][w][64 + lane] = pn;                                           \
        __syncwarp();                                                           \
        if (lane < 24) {                                                        \
            float4 v = ((const float4*)stage[bb][w])[lane];                     \
            st_cluster_v4((DA) + lane * 16, v);                                 \
        }                                                                       \
        __syncwarp();                                                           \
        if (lane == 0) mbar_arrive_remote(DB);                                  \
    }

// Phase C for batch bb (warp 0 only, caller guards).
#define GRU_C(bb, P, GR, GZ, GN, HOUT, GPR, GPZ, GPN, k)                        \
    {                                                                           \
        float sr = 0.f, sz = 0.f, sn = 0.f;                                     \
        _Pragma("unroll")                                                       \
        for (int s = 0; s < 8; s++) {                                           \
            sr += accb[bb][P][s][lane];                                         \
            sz += accb[bb][P][s][32 + lane];                                    \
            sn += accb[bb][P][s][64 + lane];                                    \
        }                                                                       \
        float hold = hloc[bb][P][lane];                                         \
        float r = fast_sigmoid(GR + sr + bhr);                                  \
        float z = fast_sigmoid(GZ + sz + bhz);                                  \
        float n = fast_tanh(GN + r * (sn + bhn));                               \
        float hnew = (1.f - z) * n + z * hold;                                  \
        hloc[bb][(P) ^ 1][lane] = hnew;                                         \
        HOUT[(size_t)(k) * H_] = hnew;                                          \
        if ((k) + 1 < T_) {                                                     \
            size_t o = (size_t)((k) + 1) * H_ + J;                              \
            GR = GPR[o]; GZ = GPZ[o]; GN = GPN[o];                              \
        }                                                                       \
    }

#define GRU_STEP(k, P)                                                          \
    {                                                                           \
        __syncthreads();                                                        \
        GRU_AB(0, P, (P) ? da01 : da00, (P) ? db01 : db00);                     \
        GRU_AB(1, P, (P) ? da11 : da10, (P) ? db11 : db10);                     \
        if (w == 0) {                                                           \
            if (P) { mbar_wait(bl01, ph01); ph01 ^= 1; }                        \
            else   { mbar_wait(bl00, ph00); ph00 ^= 1; }                        \
            GRU_C(0, P, gr0, gz0, gn0, hout0, g_r0, g_z0, g_n0, k);             \
            if (P) { mbar_wait(bl11, ph11); ph11 ^= 1; }                        \
            else   { mbar_wait(bl10, ph10); ph10 ^= 1; }                        \
            GRU_C(1, P, gr1, gz1, gn1, hout1, g_r1, g_z1, g_n1, k);             \
        }                                                                       \
    }

    for (int k = 0; k < T_; k += 2) {
        GRU_STEP(k, 0);
        GRU_STEP(k + 1, 1);
    }
#undef GRU_STEP
#undef GRU_C
#undef GRU_AB
    cluster_sync_();    // no CTA exits while peer traffic could be in flight
}

// ---------------------------------------------------------------------------
// Windowed soft time attention + ctx construction (unchanged).
// ---------------------------------------------------------------------------
#define ATT_ROWS 160
__global__ __launch_bounds__(256)
void attn_kernel(const float* __restrict__ hseq, const float* __restrict__ t,
                 float* __restrict__ ctx)
{
    extern __shared__ float sm[];
    float4* hsm  = (float4*)sm;
    float*  tsm  = sm + ATT_ROWS * H_;
    float*  hgsm = tsm + ATT_ROWS;
    float*  wbuf = hgsm + H_;

    const int b   = blockIdx.y;
    const int k0  = blockIdx.x * 32;
    const int r0  = k0 - 64;
    const int tid = threadIdx.x;
    const float4* hseq4 = (const float4*)(hseq + (size_t)b * T_ * H_);

    for (int idx = tid; idx < ATT_ROWS * 64; idx += 256) {
        int row = idx >> 6, c4 = idx & 63;
        int g = r0 + row;
        hsm[idx] = (g >= 0 && g < T_) ? hseq4[(size_t)g * 64 + c4]
                                      : make_float4(0.f, 0.f, 0.f, 0.f);
    }
    if (tid < ATT_ROWS) {
        int g = r0 + tid;
        tsm[tid] = (g >= 0 && g < T_) ? t[(size_t)b * T_ + g] : 0.f;
    }
    hgsm[tid] = hseq[((size_t)b * T_ + (T_ - 1)) * H_ + tid];
    __syncthreads();

    const int w = tid >> 5, lane = tid & 31;
    float* wb = wbuf + w * 132;

    for (int kk = 0; kk < 4; kk++) {
        int k = k0 + w * 4 + kk;
        float tk = tsm[k - r0];
        float sum = 0.f;
#pragma unroll
        for (int i = 0; i < 5; i++) {
            int l = lane + 32 * i;
            if (l < 129) {
                int jj = k - 64 + l;
                float wv = 0.f;
                if (jj >= 0 && jj < T_) {
                    float d = 2048.f * (tk - tsm[jj - r0]);
                    wv = __expf(-d * d);
                }
                wb[l] = wv;
                sum += wv;
            }
        }
#pragma unroll
        for (int off = 16; off; off >>= 1) sum += __shfl_xor_sync(0xffffffffu, sum, off);
        float thresh = sum * 1e-12f;

        float4 a0 = make_float4(0.f, 0.f, 0.f, 0.f);
        float4 a1 = make_float4(0.f, 0.f, 0.f, 0.f);
        for (int l = 0; l < 129; l++) {
            float wv = wb[l];
            if (wv > thresh) {
                const float4* row = hsm + (size_t)(l + (k - 64) - r0) * 64;
                float4 h0 = row[lane], h1 = row[32 + lane];
                a0.x = fmaf(wv, h0.x, a0.x); a0.y = fmaf(wv, h0.y, a0.y);
                a0.z = fmaf(wv, h0.z, a0.z); a0.w = fmaf(wv, h0.w, a0.w);
                a1.x = fmaf(wv, h1.x, a1.x); a1.y = fmaf(wv, h1.y, a1.y);
                a1.z = fmaf(wv, h1.z, a1.z); a1.w = fmaf(wv, h1.w, a1.w);
            }
        }
        float inv = 1.f / sum;
        if (k < TM1) {
            float* dst = ctx + ((size_t)b * TM1 + k) * (H_ + 1);
            int d0 = lane * 4, d1 = 128 + lane * 4;
            dst[d0 + 0] = a0.x * inv + hgsm[d0 + 0];
            dst[d0 + 1] = a0.y * inv + hgsm[d0 + 1];
            dst[d0 + 2] = a0.z * inv + hgsm[d0 + 2];
            dst[d0 + 3] = a0.w * inv + hgsm[d0 + 3];
            dst[d1 + 0] = a1.x * inv + hgsm[d1 + 0];
            dst[d1 + 1] = a1.y * inv + hgsm[d1 + 1];
            dst[d1 + 2] = a1.z * inv + hgsm[d1 + 2];
            dst[d1 + 3] = a1.w * inv + hgsm[d1 + 3];
            if (lane == 0) dst[H_] = tk;
        }
    }
}

// ---------------------------------------------------------------------------
// Init head — 4-way output ILP per warp.
// ---------------------------------------------------------------------------
__global__ __launch_bounds__(256)
void init_head_kernel(const float* __restrict__ ctx, const float* __restrict__ Wi1,
                      const float* __restrict__ bi1, const float* __restrict__ Wi2,
                      const float* __restrict__ bi2, float* __restrict__ m0,
                      float* __restrict__ s0)
{
    const int b = blockIdx.x, tid = threadIdx.x;
    const int w = tid >> 5, lane = tid & 31;
    __shared__ float c0[H_], hi[H_];
    c0[tid] = ctx[((size_t)b * TM1 + 0) * (H_ + 1) + tid];
    __syncthreads();
    for (int o0 = 0; o0 < 32; o0 += 4) {
        int o = w * 32 + o0;
        float s0a = 0.f, s1a = 0.f, s2a = 0.f, s3a = 0.f;
        const float* w0 = Wi1 + (size_t)(o + 0) * H_;
        const float* w1 = Wi1 + (size_t)(o + 1) * H_;
        const float* w2 = Wi1 + (size_t)(o + 2) * H_;
        const float* w3 = Wi1 + (size_t)(o + 3) * H_;
#pragma unroll
        for (int i = 0; i < 8; i++) {
            int d = lane + 32 * i;
            float cv = c0[d];
            s0a = fmaf(cv, w0[d], s0a);
            s1a = fmaf(cv, w1[d], s1a);
            s2a = fmaf(cv, w2[d], s2a);
            s3a = fmaf(cv, w3[d], s3a);
        }
#pragma unroll
        for (int off = 16; off; off >>= 1) {
            s0a += __shfl_xor_sync(0xffffffffu, s0a, off);
            s1a += __shfl_xor_sync(0xffffffffu, s1a, off);
            s2a += __shfl_xor_sync(0xffffffffu, s2a, off);
            s3a += __shfl_xor_sync(0xffffffffu, s3a, off);
        }
        if (lane == 0) {
            hi[o + 0] = siluf_(s0a + bi1[o + 0]);
            hi[o + 1] = siluf_(s1a + bi1[o + 1]);
            hi[o + 2] = siluf_(s2a + bi1[o + 2]);
            hi[o + 3] = siluf_(s3a + bi1[o + 3]);
        }
    }
    __syncthreads();
    for (int o0 = 0; o0 < 8; o0 += 4) {
        int o = w * 8 + o0;
        float s0a = 0.f, s1a = 0.f, s2a = 0.f, s3a = 0.f;
        const float* w0 = Wi2 + (size_t)(o + 0) * H_;
        const float* w1 = Wi2 + (size_t)(o + 1) * H_;
        const float* w2 = Wi2 + (size_t)(o + 2) * H_;
        const float* w3 = Wi2 + (size_t)(o + 3) * H_;
#pragma unroll
        for (int i = 0; i < 8; i++) {
            int d = lane + 32 * i;
            float hv = hi[d];
            s0a = fmaf(hv, w0[d], s0a);
            s1a = fmaf(hv, w1[d], s1a);
            s2a = fmaf(hv, w2[d], s2a);
            s3a = fmaf(hv, w3[d], s3a);
        }
#pragma unroll
        for (int off = 16; off; off >>= 1) {
            s0a += __shfl_xor_sync(0xffffffffu, s0a, off);
            s1a += __shfl_xor_sync(0xffffffffu, s1a, off);
            s2a += __shfl_xor_sync(0xffffffffu, s2a, off);
            s3a += __shfl_xor_sync(0xffffffffu, s3a, off);
        }
        if (lane == 0) {
            float vv[4] = { s0a, s1a, s2a, s3a };
#pragma unroll
            for (int u2 = 0; u2 < 4; u2++) {
                int oo = o + u2;
                float a = vv[u2] + bi2[oo];
                if (oo < C_) m0[b * C_ + oo] = a;
                else         s0[b * C_ + (oo - C_)] = softplusf_(a) + 1e-6f;
            }
        }
    }
}

// ---------------------------------------------------------------------------
// OU posterior (unchanged).
// ---------------------------------------------------------------------------
__global__ __launch_bounds__(256)
void ou_kernel(const float* __restrict__ params, const float* __restrict__ t,
               const float* __restrict__ eps, const float* __restrict__ eps0,
               const float* __restrict__ m0, const float* __restrict__ s0,
               float* __restrict__ outc, double* __restrict__ part)
{
    const int gwarp = (blockIdx.x * blockDim.x + threadIdx.x) >> 5;
    const int lane  = threadIdx.x & 31;
    const int b = gwarp >> 5, ch = gwarp & 31;

    const float m0v = m0[b * C_ + ch];
    const float s0v = s0[b * C_ + ch];
    const float c0  = m0v + s0v * eps0[b * C_ + ch];

    double acc = 0.0;
    if (lane == 0) {
        float s0c = fmaxf(s0v, 1e-12f);
        float zn  = (c0 - m0v) / s0c;
        acc = -0.5 * ((double)(zn * zn + 2.f * logf(s0c)) + LOG2PI);
        outc[((size_t)b * T_ + 0) * C_ + ch] = c0;
    }

    float phi_carry = 1.f, s_carry = 0.f, c_carry = c0;
    const float* tb = t + (size_t)b * T_;

    for (int chunk = 0; chunk < 64; chunk++) {
        int k = chunk * 32 + lane;
        bool valid = (k < TM1);
        float A = 1.f, bk = 0.f, Q = 1.f, mu = 0.f;
        if (valid) {
            size_t base = (size_t)b * TM1 + k;
            mu = params[base * (3 * C_) + ch];
            float kap = softplusf_(params[base * (3 * C_) + C_ + ch]) + 1e-6f;
            float sig = softplusf_(params[base * (3 * C_) + 2 * C_ + ch]) + 1e-6f;
            float dt  = fmaxf(tb[k + 1] - tb[k], 1e-6f);
            A = expf(-kap * dt);
            float two = 2.f * kap * dt;
            float Qe  = sig * sig * (1.f - expf(-two)) / fmaxf(2.f * kap, 1e-12f);
            float kd  = kap * dt;
            float Qt  = sig * sig * dt * (1.f - kd + two * two * (1.f / 6.f));
            Q = (two < 1e-6f) ? Qt : Qe;
            bk = (1.f - A) * mu + eps[base * C_ + ch] * sqrtf(fmaxf(Q, 1e-12f));
        }
        float pA = A;
#pragma unroll
        for (int d = 1; d < 32; d <<= 1) {
            float v = __shfl_up_sync(0xffffffffu, pA, d);
            if (lane >= d) pA *= v;
        }
        float phi = phi_carry * pA;
        float s   = valid ? bk / fmaxf(phi, 1e-20f) : 0.f;
        float ps  = s;
#pragma unroll
        for (int d = 1; d < 32; d <<= 1) {
            float v = __shfl_up_sync(0xffffffffu, ps, d);
            if (lane >= d) ps += v;
        }
        float Sn = s_carry + ps;
        float cn = phi * (c0 + Sn);
        float cp = __shfl_up_sync(0xffffffffu, cn, 1);
        if (lane == 0) cp = c_carry;
        if (valid) {
            float varQ = fmaxf(Q, 1e-12f);
            float mean = mu + A * (cp - mu);
            float rs   = cn - mean;
            acc += -0.5 * ((double)(rs * rs / varQ + logf(varQ)) + LOG2PI);
            outc[((size_t)b * T_ + k + 1) * C_ + ch] = cn;
        }
        phi_carry = __shfl_sync(0xffffffffu, phi, 31);
        s_carry   = __shfl_sync(0xffffffffu, Sn, 31);
        c_carry   = __shfl_sync(0xffffffffu, cn, 31);
    }
#pragma unroll
    for (int off = 16; off >= 1; off >>= 1)
        acc += __shfl_down_sync(0xffffffffu, acc, off);
    if (lane == 0) part[b * C_ + ch] = acc;
}

__global__ void finalize_q(const double* __restrict__ part, float* __restrict__ outq)
{
    int tid = threadIdx.x;
    int b = tid >> 5, lane = tid & 31;
    double v = part[b * C_ + lane];
#pragma unroll
    for (int off = 16; off >= 1; off >>= 1)
        v += __shfl_down_sync(0xffffffffu, v, off);
    if (lane == 0) outq[b] = (float)v;
}

// ---------------------------------------------------------------------------
// Launch
// ---------------------------------------------------------------------------
extern "C" void kernel_launch(void* const* d_in, const int* in_sizes, int n_in,
                              void* d_out, int out_size)
{
    const float* x    = (const float*)d_in[0];
    const float* t    = (const float*)d_in[1];
    const float* eps0 = (const float*)d_in[2];
    const float* eps  = (const float*)d_in[3];
    const float* W_ih = (const float*)d_in[4];
    const float* W_hh = (const float*)d_in[5];
    const float* b_ih = (const float*)d_in[6];
    const float* b_hh = (const float*)d_in[7];
    const float* Wi1  = (const float*)d_in[8];
    const float* bi1  = (const float*)d_in[9];
    const float* Wi2  = (const float*)d_in[10];
    const float* bi2  = (const float*)d_in[11];
    const float* Ws1  = (const float*)d_in[12];
    const float* bs1  = (const float*)d_in[13];
    const float* Ws2  = (const float*)d_in[14];
    const float* bs2  = (const float*)d_in[15];
    const float* Ws3  = (const float*)d_in[16];
    const float* bs3  = (const float*)d_in[17];

    float* outc = (float*)d_out;
    float* outq = outc + (size_t)B_ * T_ * C_;

    float *gi, *hseq, *ctx, *hs1, *hs2, *par, *m0, *s0;
    double* part;
    cudaGetSymbolAddress((void**)&gi,   g_gi);
    cudaGetSymbolAddress((void**)&hseq, g_hseq);
    cudaGetSymbolAddress((void**)&ctx,  g_ctx);
    cudaGetSymbolAddress((void**)&hs1,  g_hs1);
    cudaGetSymbolAddress((void**)&hs2,  g_hs2);
    cudaGetSymbolAddress((void**)&par,  g_par);
    cudaGetSymbolAddress((void**)&m0,   g_m0);
    cudaGetSymbolAddress((void**)&s0,   g_s0);
    cudaGetSymbolAddress((void**)&part, g_part);

    const int M1 = B_ * T_;    // 16384
    const int M2 = B_ * TM1;   // 16376

    // 1-3. gi per-gate planes (keeps GRU in the ncu-captured launch slot 4)
    for (int g = 0; g < 3; g++) {
        gemm_tn<0><<<dim3(H_ / 64, (M1 + 127) / 128), 256>>>(
            x, W_ih + (size_t)g * H_ * X_, b_ih + g * H_,
            gi + (size_t)g * B_ * T_ * H_, M1, H_, X_);
    }

    // 4. GRU scan: 4 clusters x 8 CTAs, reduce-scatter + 2-batch interleave
    gru_kernel<<<32, 256>>>(gi, W_hh, b_hh, hseq);

    // 5. attention + ctx
    size_t attn_smem = (size_t)(ATT_ROWS * H_ + ATT_ROWS + H_ + 8 * 132) * sizeof(float);
    cudaFuncSetAttribute(attn_kernel, cudaFuncAttributeMaxDynamicSharedMemorySize,
                         (int)attn_smem);
    attn_kernel<<<dim3(T_ / 32, B_), 256, attn_smem>>>(hseq, t, ctx);

    // 6. init head
    init_head_kernel<<<B_, 256>>>(ctx, Wi1, bi1, Wi2, bi2, m0, s0);

    // 7-9. step head MLP
    gemm_tn<1><<<dim3((H_ + 63) / 64, (M2 + 127) / 128), 256>>>(
        ctx, Ws1, bs1, hs1, M2, H_, H_ + 1);
    gemm_tn<1><<<dim3((H_ + 63) / 64, (M2 + 127) / 128), 256>>>(
        hs1, Ws2, bs2, hs2, M2, H_, H_);
    gemm_tn<0><<<dim3((3 * C_ + 63) / 64, (M2 + 127) / 128), 256>>>(
        hs2, Ws3, bs3, par, M2, 3 * C_, H_);

    // 10. OU posterior
    ou_kernel<<<32, 256>>>(par, t, eps, eps0, m0, s0, outc, part);

    // 11. finalize log_q
    finalize_q<<<1, 256>>>(part, outq);

    (void)in_sizes; (void)n_in; (void)out_size;
}

// round 16
// speedup vs baseline: 2.2577x; 2.2577x over previous
#include <cuda_runtime.h>
#include <cuda_bf16.h>
#include <cstdint>

// ---------------------------------------------------------------------------
// Problem shapes (fixed)
// ---------------------------------------------------------------------------
#define B_  8
#define T_  2048
#define X_  64
#define H_  256
#define C_  32
#define TM1 2047
#define LOG2PI 1.8378770664093453

typedef unsigned long long ull;

// ---------------------------------------------------------------------------
// Scratch (device globals — no allocation allowed)
// ---------------------------------------------------------------------------
__device__ float  g_gi   [3 * B_ * T_ * H_];      // 3 gate planes [g][B,T,H]
__device__ float  g_hseq [B_ * T_ * H_];
__device__ float  g_ctx  [B_ * TM1 * (H_ + 1)];
__device__ float  g_hs1  [B_ * TM1 * H_];
__device__ float  g_hs2  [B_ * TM1 * H_];
__device__ float  g_par  [B_ * TM1 * 3 * C_];
__device__ float  g_m0   [B_ * C_];
__device__ float  g_s0   [B_ * C_];
__device__ double g_part [B_ * C_];

// ---------------------------------------------------------------------------
// Helpers
// ---------------------------------------------------------------------------
__device__ __forceinline__ float softplusf_(float x) {
    return fmaxf(x, 0.f) + log1pf(expf(-fabsf(x)));
}
__device__ __forceinline__ float siluf_(float x) { return x / (1.f + expf(-x)); }
__device__ __forceinline__ float fast_sigmoid(float x) {
    return __fdividef(1.f, 1.f + __expf(-x));
}
__device__ __forceinline__ float fast_tanh(float x) {
    float xc = fminf(fmaxf(x, -15.f), 15.f);
    float e = __expf(2.f * xc);
    return __fdividef(e - 1.f, e + 1.f);
}

__device__ __forceinline__ float2 unpack_f32x2(ull v) {
    float2 r;
    asm("mov.b64 {%0,%1}, %2;" : "=f"(r.x), "=f"(r.y) : "l"(v));
    return r;
}
__device__ __forceinline__ ull pack2(float x, float y) {
    ull v;
    asm("mov.b64 %0, {%1,%2};" : "=l"(v) : "f"(x), "f"(y));
    return v;
}
__device__ __forceinline__ void fma_f32x2(ull& acc, ull a, ull b) {
    asm("fma.rn.f32x2 %0, %1, %2, %0;" : "+l"(acc) : "l"(a), "l"(b));
}
__device__ __forceinline__ void cluster_sync_() {
    asm volatile("barrier.cluster.arrive.aligned;" ::: "memory");
    asm volatile("barrier.cluster.wait.aligned;" ::: "memory");
}
__device__ __forceinline__ uint32_t smem_u32(const void* p) {
    return (uint32_t)__cvta_generic_to_shared(p);
}
__device__ __forceinline__ uint32_t mapa_u32(uint32_t laddr, unsigned rank) {
    uint32_t raddr;
    asm volatile("mapa.shared::cluster.u32 %0, %1, %2;" : "=r"(raddr) : "r"(laddr), "r"(rank));
    return raddr;
}
__device__ __forceinline__ void mbar_init(uint32_t addr, uint32_t count) {
    asm volatile("mbarrier.init.shared.b64 [%0], %1;" :: "r"(addr), "r"(count) : "memory");
}
__device__ __forceinline__ void mbar_expect_tx(uint32_t addr, uint32_t bytes) {
    asm volatile("mbarrier.arrive.expect_tx.shared.b64 _, [%0], %1;"
                 :: "r"(addr), "r"(bytes) : "memory");
}
__device__ __forceinline__ void mbar_wait(uint32_t addr, uint32_t parity) {
    asm volatile(
        "{\n\t"
        ".reg .pred P;\n\t"
        "WL_%=:\n\t"
        "mbarrier.try_wait.parity.acquire.cluster.shared::cta.b64 P, [%0], %1, 0x989680;\n\t"
        "@!P bra WL_%=;\n\t"
        "}" :: "r"(addr), "r"(parity) : "memory");
}
// Bulk DSMEM copy: local smem -> peer smem, completion as tx-bytes on the
// peer's mbarrier (fused data+signal; no release fence, no arrival storm).
__device__ __forceinline__ void bulk_copy_cluster(uint32_t dst_cluster, uint32_t src_cta,
                                                  uint32_t bytes, uint32_t mbar_cluster) {
    asm volatile(
        "cp.async.bulk.shared::cluster.shared::cta.mbarrier::complete_tx::bytes "
        "[%0], [%1], %2, [%3];"
        :: "r"(dst_cluster), "r"(src_cta), "r"(bytes), "r"(mbar_cluster) : "memory");
}
__device__ __forceinline__ void bulk_commit() {
    asm volatile("cp.async.bulk.commit_group;" ::: "memory");
}
__device__ __forceinline__ void bulk_wait_read1() {
    asm volatile("cp.async.bulk.wait_group.read 1;" ::: "memory");
}

// ---------------------------------------------------------------------------
// GEMM: C[M,N] = act( A[M,K] * B[N,K]^T + bias[N] )  (unchanged)
// ---------------------------------------------------------------------------
template <int ACT>
__global__ __launch_bounds__(256)
void gemm_tn(const float* __restrict__ A, const float* __restrict__ B,
             const float* __restrict__ bias, float* __restrict__ C,
             int M, int N, int K)
{
    __shared__ float As[16][132];
    __shared__ float Bs[16][68];
    const int tid = threadIdx.x;
    const int tx = tid & 15, ty = tid >> 4;
    const int bm = blockIdx.y * 128, bn = blockIdx.x * 64;

    ull acc[4][4];
#pragma unroll
    for (int i = 0; i < 4; i++)
#pragma unroll
        for (int j = 0; j < 4; j++) acc[i][j] = 0ULL;

    for (int k0 = 0; k0 < K; k0 += 16) {
#pragma unroll
        for (int i = 0; i < 8; i++) {
            int e = tid + i * 256;
            int r = e >> 4, c = e & 15;
            int ga = bm + r, gc = k0 + c;
            float v = (ga < M && gc < K) ? A[(size_t)ga * K + gc] : 0.f;
            As[c][(r & 15) * 8 + (r >> 4)] = v;
        }
#pragma unroll
        for (int i = 0; i < 4; i++) {
            int e = tid + i * 256;
            int r = e >> 4, c = e & 15;
            int gb = bn + r, gc = k0 + c;
            Bs[c][r] = (gb < N && gc < K) ? B[(size_t)gb * K + gc] : 0.f;
        }
        __syncthreads();
#pragma unroll
        for (int kk = 0; kk < 16; kk++) {
            float4 a0 = *(const float4*)&As[kk][ty * 8];
            float4 a1 = *(const float4*)&As[kk][ty * 8 + 4];
            float4 bq = *(const float4*)&Bs[kk][tx * 4];
            ull ap[4] = { pack2(a0.x, a0.y), pack2(a0.z, a0.w),
                          pack2(a1.x, a1.y), pack2(a1.z, a1.w) };
            ull bd[4] = { pack2(bq.x, bq.x), pack2(bq.y, bq.y),
                          pack2(bq.z, bq.z), pack2(bq.w, bq.w) };
#pragma unroll
            for (int P = 0; P < 4; P++)
#pragma unroll
                for (int j = 0; j < 4; j++)
                    fma_f32x2(acc[P][j], ap[P], bd[j]);
        }
        __syncthreads();
    }

#pragma unroll
    for (int P = 0; P < 4; P++) {
        float lo[4], hi[4];
#pragma unroll
        for (int j = 0; j < 4; j++) {
            float2 u = unpack_f32x2(acc[P][j]);
            lo[j] = u.x; hi[j] = u.y;
        }
#pragma unroll
        for (int half = 0; half < 2; half++) {
            int m = bm + ty + 32 * P + 16 * half;
            if (m >= M) continue;
            float* vv = half ? hi : lo;
            float* dst = C + (size_t)m * N;
#pragma unroll
            for (int j = 0; j < 4; j++) {
                int n = bn + tx * 4 + j;
                if (n >= N) continue;
                float v = vv[j] + bias[n];
                if (ACT == 1) v = siluf_(v);
                dst[n] = v;
            }
        }
    }
}

// ---------------------------------------------------------------------------
// GRU scan — reduce-scatter (R13 structure) with BULK-DMA exchange.
// 8 clusters (1/batch) x 8 CTAs x 256 threads.
// CTA r owns h chunk [32r,32r+32) (local forever). Thread tid holds W rows
// {tid, H+tid, 2H+tid} over cols [32r,32r+32) in regs.
// Per step (buf P):
//   __syncthreads (hloc[P] ready)
//   [warp0 lane0] expect_tx(mbar[P], 3072)       -- 1 arrival + 3072 tx bytes
//   A: 48 f32x2 partial dots from hloc[P]
//   B: per warp w: wait_group.read<=1 (stage[P] safe) -> STS partials to
//      stage[P][w] -> syncwarp -> lane0: cp.async.bulk 384B -> peer w's
//      accb[P][rank] with complete_tx on peer w's mbar[P]; commit_group.
//   C (warp0): wait parity(mbar[P]) -> sum 8 sources -> gates -> hloc[P^1],
//      coalesced hseq store, gi prefetch.
// stage double-buffered (DMA reads source async; wait_group.read guards
// reuse at distance 2). Every send is consumed same-step by the peer's
// wait; final cluster_sync has all warp0s arriving post-wait, so all DMAs
// have landed before any CTA exits.
// ---------------------------------------------------------------------------
__global__ void __cluster_dims__(8, 1, 1) __launch_bounds__(256, 1)
gru_kernel(const float* __restrict__ gi, const float* __restrict__ Whh,
           const float* __restrict__ bhh, float* __restrict__ hseq)
{
    __shared__ __align__(16) float hloc[2][32];
    __shared__ __align__(16) float accb[2][8][96];   // [buf][src CTA][g*32+jl]
    __shared__ __align__(16) float stage[2][8][96];  // [buf][warp=dest]
    __shared__ __align__(8) ull mbar[2];
    const int tid  = threadIdx.x;
    const int w    = tid >> 5;
    const int lane = tid & 31;
    const unsigned rank = (unsigned)(blockIdx.x & 7);
    const int b    = blockIdx.x >> 3;

    // W column-slice: rows g*H + tid, cols [32*rank, 32*rank+32)
    ull Wr[16], Wz[16], Wn[16];
    {
        const ull* wr = (const ull*)(Whh + ((size_t)(0 * H_ + tid)) * H_ + 32 * rank);
        const ull* wz = (const ull*)(Whh + ((size_t)(1 * H_ + tid)) * H_ + 32 * rank);
        const ull* wn = (const ull*)(Whh + ((size_t)(2 * H_ + tid)) * H_ + 32 * rank);
#pragma unroll
        for (int x = 0; x < 16; x++) { Wr[x] = wr[x]; Wz[x] = wz[x]; Wn[x] = wn[x]; }
    }
    const int J = (int)rank * 32 + lane;     // warp0's output index
    const float bhr = bhh[0 * H_ + J];
    const float bhz = bhh[1 * H_ + J];
    const float bhn = bhh[2 * H_ + J];
    const float* g_r = gi + 0 * (size_t)B_ * T_ * H_ + (size_t)b * T_ * H_;
    const float* g_z = gi + 1 * (size_t)B_ * T_ * H_ + (size_t)b * T_ * H_;
    const float* g_n = gi + 2 * (size_t)B_ * T_ * H_ + (size_t)b * T_ * H_;
    float gr = g_r[J], gz = g_z[J], gn = g_n[J];
    float* hout = hseq + (size_t)b * T_ * H_ + rank * 32 + lane;

    if (tid < 2) mbar_init(smem_u32(&mbar[tid]), 1);   // 1 arrival: the expect_tx
    if (tid < 32) hloc[0][tid] = 0.f;
    __syncthreads();
    cluster_sync_();    // barrier inits + zeros visible before remote traffic

    // Warp w delivers into peer w's accb[P][rank]; signal on peer w's mbar[P].
    const uint32_t da0 = mapa_u32(smem_u32(&accb[0][rank][0]), (unsigned)w);
    const uint32_t da1 = mapa_u32(smem_u32(&accb[1][rank][0]), (unsigned)w);
    const uint32_t db0 = mapa_u32(smem_u32(&mbar[0]), (unsigned)w);
    const uint32_t db1 = mapa_u32(smem_u32(&mbar[1]), (unsigned)w);
    const uint32_t bl0 = smem_u32(&mbar[0]);
    const uint32_t bl1 = smem_u32(&mbar[1]);
    const uint32_t st0 = smem_u32(&stage[0][0][0]);
    const uint32_t st1 = smem_u32(&stage[1][0][0]);
    uint32_t ph0 = 0, ph1 = 0;

#define GRU_STEP(k, P)                                                          \
    {                                                                           \
        __syncthreads();                      /* hloc[P] ready for all warps */ \
        if (w == 0 && lane == 0)                                                \
            mbar_expect_tx((P) ? bl1 : bl0, 3072);                              \
        const ull* hp = (const ull*)hloc[P];                                    \
        ull ar = 0ULL, az = 0ULL, an = 0ULL;                                    \
        _Pragma("unroll")                                                       \
        for (int x = 0; x < 16; x++) {                                          \
            ull h2 = hp[x];                   /* broadcast LDS, conflict-free */\
            fma_f32x2(ar, Wr[x], h2);                                           \
            fma_f32x2(az, Wz[x], h2);                                           \
            fma_f32x2(an, Wn[x], h2);                                           \
        }                                                                       \
        float2 u;                                                               \
        u = unpack_f32x2(ar); float pr = u.x + u.y;                             \
        u = unpack_f32x2(az); float pz = u.x + u.y;                             \
        u = unpack_f32x2(an); float pn = u.x + u.y;                             \
        if (lane == 0) bulk_wait_read1();     /* stage[P] free (dist-2 reuse) */\
        __syncwarp();                                                           \
        stage[P][w][lane]      = pr;                                            \
        stage[P][w][32 + lane] = pz;                                            \
        stage[P][w][64 + lane] = pn;                                            \
        __syncwarp();                                                           \
        if (lane == 0) {                                                        \
            bulk_copy_cluster((P) ? da1 : da0,                                  \
                              ((P) ? st1 : st0) + w * 384, 384,                 \
                              (P) ? db1 : db0);                                 \
            bulk_commit();                                                      \
        }                                                                       \
        if (w == 0) {                                                           \
            if (P) { mbar_wait(bl1, ph1); ph1 ^= 1; }                           \
            else   { mbar_wait(bl0, ph0); ph0 ^= 1; }                           \
            float sr = 0.f, sz = 0.f, sn = 0.f;                                 \
            _Pragma("unroll")                                                   \
            for (int s = 0; s < 8; s++) {                                       \
                sr += accb[P][s][lane];                                         \
                sz += accb[P][s][32 + lane];                                    \
                sn += accb[P][s][64 + lane];                                    \
            }                                                                   \
            float hold = hloc[P][lane];                                         \
            float r = fast_sigmoid(gr + sr + bhr);                              \
            float z = fast_sigmoid(gz + sz + bhz);                              \
            float n = fast_tanh(gn + r * (sn + bhn));                           \
            float hnew = (1.f - z) * n + z * hold;                              \
            hloc[(P) ^ 1][lane] = hnew;                                         \
            hout[(size_t)(k) * H_] = hnew;    /* coalesced 128B row */          \
            if ((k) + 1 < T_) {                                                 \
                size_t o = (size_t)((k) + 1) * H_ + J;                          \
                gr = g_r[o]; gz = g_z[o]; gn = g_n[o];                          \
            }                                                                   \
        }                                                                       \
    }

    for (int k = 0; k < T_; k += 2) {
        GRU_STEP(k, 0);
        GRU_STEP(k + 1, 1);
    }
#undef GRU_STEP
    cluster_sync_();    // all warp0s passed final wait => all DMAs landed
}

// ---------------------------------------------------------------------------
// Windowed soft time attention + ctx construction (unchanged).
// ---------------------------------------------------------------------------
#define ATT_ROWS 160
__global__ __launch_bounds__(256)
void attn_kernel(const float* __restrict__ hseq, const float* __restrict__ t,
                 float* __restrict__ ctx)
{
    extern __shared__ float sm[];
    float4* hsm  = (float4*)sm;
    float*  tsm  = sm + ATT_ROWS * H_;
    float*  hgsm = tsm + ATT_ROWS;
    float*  wbuf = hgsm + H_;

    const int b   = blockIdx.y;
    const int k0  = blockIdx.x * 32;
    const int r0  = k0 - 64;
    const int tid = threadIdx.x;
    const float4* hseq4 = (const float4*)(hseq + (size_t)b * T_ * H_);

    for (int idx = tid; idx < ATT_ROWS * 64; idx += 256) {
        int row = idx >> 6, c4 = idx & 63;
        int g = r0 + row;
        hsm[idx] = (g >= 0 && g < T_) ? hseq4[(size_t)g * 64 + c4]
                                      : make_float4(0.f, 0.f, 0.f, 0.f);
    }
    if (tid < ATT_ROWS) {
        int g = r0 + tid;
        tsm[tid] = (g >= 0 && g < T_) ? t[(size_t)b * T_ + g] : 0.f;
    }
    hgsm[tid] = hseq[((size_t)b * T_ + (T_ - 1)) * H_ + tid];
    __syncthreads();

    const int w = tid >> 5, lane = tid & 31;
    float* wb = wbuf + w * 132;

    for (int kk = 0; kk < 4; kk++) {
        int k = k0 + w * 4 + kk;
        float tk = tsm[k - r0];
        float sum = 0.f;
#pragma unroll
        for (int i = 0; i < 5; i++) {
            int l = lane + 32 * i;
            if (l < 129) {
                int jj = k - 64 + l;
                float wv = 0.f;
                if (jj >= 0 && jj < T_) {
                    float d = 2048.f * (tk - tsm[jj - r0]);
                    wv = __expf(-d * d);
                }
                wb[l] = wv;
                sum += wv;
            }
        }
#pragma unroll
        for (int off = 16; off; off >>= 1) sum += __shfl_xor_sync(0xffffffffu, sum, off);
        float thresh = sum * 1e-12f;

        float4 a0 = make_float4(0.f, 0.f, 0.f, 0.f);
        float4 a1 = make_float4(0.f, 0.f, 0.f, 0.f);
        for (int l = 0; l < 129; l++) {
            float wv = wb[l];
            if (wv > thresh) {
                const float4* row = hsm + (size_t)(l + (k - 64) - r0) * 64;
                float4 h0 = row[lane], h1 = row[32 + lane];
                a0.x = fmaf(wv, h0.x, a0.x); a0.y = fmaf(wv, h0.y, a0.y);
                a0.z = fmaf(wv, h0.z, a0.z); a0.w = fmaf(wv, h0.w, a0.w);
                a1.x = fmaf(wv, h1.x, a1.x); a1.y = fmaf(wv, h1.y, a1.y);
                a1.z = fmaf(wv, h1.z, a1.z); a1.w = fmaf(wv, h1.w, a1.w);
            }
        }
        float inv = 1.f / sum;
        if (k < TM1) {
            float* dst = ctx + ((size_t)b * TM1 + k) * (H_ + 1);
            int d0 = lane * 4, d1 = 128 + lane * 4;
            dst[d0 + 0] = a0.x * inv + hgsm[d0 + 0];
            dst[d0 + 1] = a0.y * inv + hgsm[d0 + 1];
            dst[d0 + 2] = a0.z * inv + hgsm[d0 + 2];
            dst[d0 + 3] = a0.w * inv + hgsm[d0 + 3];
            dst[d1 + 0] = a1.x * inv + hgsm[d1 + 0];
            dst[d1 + 1] = a1.y * inv + hgsm[d1 + 1];
            dst[d1 + 2] = a1.z * inv + hgsm[d1 + 2];
            dst[d1 + 3] = a1.w * inv + hgsm[d1 + 3];
            if (lane == 0) dst[H_] = tk;
        }
    }
}

// ---------------------------------------------------------------------------
// Init head — 4-way output ILP per warp.
// ---------------------------------------------------------------------------
__global__ __launch_bounds__(256)
void init_head_kernel(const float* __restrict__ ctx, const float* __restrict__ Wi1,
                      const float* __restrict__ bi1, const float* __restrict__ Wi2,
                      const float* __restrict__ bi2, float* __restrict__ m0,
                      float* __restrict__ s0)
{
    const int b = blockIdx.x, tid = threadIdx.x;
    const int w = tid >> 5, lane = tid & 31;
    __shared__ float c0[H_], hi[H_];
    c0[tid] = ctx[((size_t)b * TM1 + 0) * (H_ + 1) + tid];
    __syncthreads();
    for (int o0 = 0; o0 < 32; o0 += 4) {
        int o = w * 32 + o0;
        float s0a = 0.f, s1a = 0.f, s2a = 0.f, s3a = 0.f;
        const float* w0 = Wi1 + (size_t)(o + 0) * H_;
        const float* w1 = Wi1 + (size_t)(o + 1) * H_;
        const float* w2 = Wi1 + (size_t)(o + 2) * H_;
        const float* w3 = Wi1 + (size_t)(o + 3) * H_;
#pragma unroll
        for (int i = 0; i < 8; i++) {
            int d = lane + 32 * i;
            float cv = c0[d];
            s0a = fmaf(cv, w0[d], s0a);
            s1a = fmaf(cv, w1[d], s1a);
            s2a = fmaf(cv, w2[d], s2a);
            s3a = fmaf(cv, w3[d], s3a);
        }
#pragma unroll
        for (int off = 16; off; off >>= 1) {
            s0a += __shfl_xor_sync(0xffffffffu, s0a, off);
            s1a += __shfl_xor_sync(0xffffffffu, s1a, off);
            s2a += __shfl_xor_sync(0xffffffffu, s2a, off);
            s3a += __shfl_xor_sync(0xffffffffu, s3a, off);
        }
        if (lane == 0) {
            hi[o + 0] = siluf_(s0a + bi1[o + 0]);
            hi[o + 1] = siluf_(s1a + bi1[o + 1]);
            hi[o + 2] = siluf_(s2a + bi1[o + 2]);
            hi[o + 3] = siluf_(s3a + bi1[o + 3]);
        }
    }
    __syncthreads();
    for (int o0 = 0; o0 < 8; o0 += 4) {
        int o = w * 8 + o0;
        float s0a = 0.f, s1a = 0.f, s2a = 0.f, s3a = 0.f;
        const float* w0 = Wi2 + (size_t)(o + 0) * H_;
        const float* w1 = Wi2 + (size_t)(o + 1) * H_;
        const float* w2 = Wi2 + (size_t)(o + 2) * H_;
        const float* w3 = Wi2 + (size_t)(o + 3) * H_;
#pragma unroll
        for (int i = 0; i < 8; i++) {
            int d = lane + 32 * i;
            float hv = hi[d];
            s0a = fmaf(hv, w0[d], s0a);
            s1a = fmaf(hv, w1[d], s1a);
            s2a = fmaf(hv, w2[d], s2a);
            s3a = fmaf(hv, w3[d], s3a);
        }
#pragma unroll
        for (int off = 16; off; off >>= 1) {
            s0a += __shfl_xor_sync(0xffffffffu, s0a, off);
            s1a += __shfl_xor_sync(0xffffffffu, s1a, off);
            s2a += __shfl_xor_sync(0xffffffffu, s2a, off);
            s3a += __shfl_xor_sync(0xffffffffu, s3a, off);
        }
        if (lane == 0) {
            float vv[4] = { s0a, s1a, s2a, s3a };
#pragma unroll
            for (int u2 = 0; u2 < 4; u2++) {
                int oo = o + u2;
                float a = vv[u2] + bi2[oo];
                if (oo < C_) m0[b * C_ + oo] = a;
                else         s0[b * C_ + (oo - C_)] = softplusf_(a) + 1e-6f;
            }
        }
    }
}

// ---------------------------------------------------------------------------
// OU posterior (unchanged).
// ---------------------------------------------------------------------------
__global__ __launch_bounds__(256)
void ou_kernel(const float* __restrict__ params, const float* __restrict__ t,
               const float* __restrict__ eps, const float* __restrict__ eps0,
               const float* __restrict__ m0, const float* __restrict__ s0,
               float* __restrict__ outc, double* __restrict__ part)
{
    const int gwarp = (blockIdx.x * blockDim.x + threadIdx.x) >> 5;
    const int lane  = threadIdx.x & 31;
    const int b = gwarp >> 5, ch = gwarp & 31;

    const float m0v = m0[b * C_ + ch];
    const float s0v = s0[b * C_ + ch];
    const float c0  = m0v + s0v * eps0[b * C_ + ch];

    double acc = 0.0;
    if (lane == 0) {
        float s0c = fmaxf(s0v, 1e-12f);
        float zn  = (c0 - m0v) / s0c;
        acc = -0.5 * ((double)(zn * zn + 2.f * logf(s0c)) + LOG2PI);
        outc[((size_t)b * T_ + 0) * C_ + ch] = c0;
    }

    float phi_carry = 1.f, s_carry = 0.f, c_carry = c0;
    const float* tb = t + (size_t)b * T_;

    for (int chunk = 0; chunk < 64; chunk++) {
        int k = chunk * 32 + lane;
        bool valid = (k < TM1);
        float A = 1.f, bk = 0.f, Q = 1.f, mu = 0.f;
        if (valid) {
            size_t base = (size_t)b * TM1 + k;
            mu = params[base * (3 * C_) + ch];
            float kap = softplusf_(params[base * (3 * C_) + C_ + ch]) + 1e-6f;
            float sig = softplusf_(params[base * (3 * C_) + 2 * C_ + ch]) + 1e-6f;
            float dt  = fmaxf(tb[k + 1] - tb[k], 1e-6f);
            A = expf(-kap * dt);
            float two = 2.f * kap * dt;
            float Qe  = sig * sig * (1.f - expf(-two)) / fmaxf(2.f * kap, 1e-12f);
            float kd  = kap * dt;
            float Qt  = sig * sig * dt * (1.f - kd + two * two * (1.f / 6.f));
            Q = (two < 1e-6f) ? Qt : Qe;
            bk = (1.f - A) * mu + eps[base * C_ + ch] * sqrtf(fmaxf(Q, 1e-12f));
        }
        float pA = A;
#pragma unroll
        for (int d = 1; d < 32; d <<= 1) {
            float v = __shfl_up_sync(0xffffffffu, pA, d);
            if (lane >= d) pA *= v;
        }
        float phi = phi_carry * pA;
        float s   = valid ? bk / fmaxf(phi, 1e-20f) : 0.f;
        float ps  = s;
#pragma unroll
        for (int d = 1; d < 32; d <<= 1) {
            float v = __shfl_up_sync(0xffffffffu, ps, d);
            if (lane >= d) ps += v;
        }
        float Sn = s_carry + ps;
        float cn = phi * (c0 + Sn);
        float cp = __shfl_up_sync(0xffffffffu, cn, 1);
        if (lane == 0) cp = c_carry;
        if (valid) {
            float varQ = fmaxf(Q, 1e-12f);
            float mean = mu + A * (cp - mu);
            float rs   = cn - mean;
            acc += -0.5 * ((double)(rs * rs / varQ + logf(varQ)) + LOG2PI);
            outc[((size_t)b * T_ + k + 1) * C_ + ch] = cn;
        }
        phi_carry = __shfl_sync(0xffffffffu, phi, 31);
        s_carry   = __shfl_sync(0xffffffffu, Sn, 31);
        c_carry   = __shfl_sync(0xffffffffu, cn, 31);
    }
#pragma unroll
    for (int off = 16; off >= 1; off >>= 1)
        acc += __shfl_down_sync(0xffffffffu, acc, off);
    if (lane == 0) part[b * C_ + ch] = acc;
}

__global__ void finalize_q(const double* __restrict__ part, float* __restrict__ outq)
{
    int tid = threadIdx.x;
    int b = tid >> 5, lane = tid & 31;
    double v = part[b * C_ + lane];
#pragma unroll
    for (int off = 16; off >= 1; off >>= 1)
        v += __shfl_down_sync(0xffffffffu, v, off);
    if (lane == 0) outq[b] = (float)v;
}

// ---------------------------------------------------------------------------
// Launch
// ---------------------------------------------------------------------------
extern "C" void kernel_launch(void* const* d_in, const int* in_sizes, int n_in,
                              void* d_out, int out_size)
{
    const float* x    = (const float*)d_in[0];
    const float* t    = (const float*)d_in[1];
    const float* eps0 = (const float*)d_in[2];
    const float* eps  = (const float*)d_in[3];
    const float* W_ih = (const float*)d_in[4];
    const float* W_hh = (const float*)d_in[5];
    const float* b_ih = (const float*)d_in[6];
    const float* b_hh = (const float*)d_in[7];
    const float* Wi1  = (const float*)d_in[8];
    const float* bi1  = (const float*)d_in[9];
    const float* Wi2  = (const float*)d_in[10];
    const float* bi2  = (const float*)d_in[11];
    const float* Ws1  = (const float*)d_in[12];
    const float* bs1  = (const float*)d_in[13];
    const float* Ws2  = (const float*)d_in[14];
    const float* bs2  = (const float*)d_in[15];
    const float* Ws3  = (const float*)d_in[16];
    const float* bs3  = (const float*)d_in[17];

    float* outc = (float*)d_out;
    float* outq = outc + (size_t)B_ * T_ * C_;

    float *gi, *hseq, *ctx, *hs1, *hs2, *par, *m0, *s0;
    double* part;
    cudaGetSymbolAddress((void**)&gi,   g_gi);
    cudaGetSymbolAddress((void**)&hseq, g_hseq);
    cudaGetSymbolAddress((void**)&ctx,  g_ctx);
    cudaGetSymbolAddress((void**)&hs1,  g_hs1);
    cudaGetSymbolAddress((void**)&hs2,  g_hs2);
    cudaGetSymbolAddress((void**)&par,  g_par);
    cudaGetSymbolAddress((void**)&m0,   g_m0);
    cudaGetSymbolAddress((void**)&s0,   g_s0);
    cudaGetSymbolAddress((void**)&part, g_part);

    const int M1 = B_ * T_;    // 16384
    const int M2 = B_ * TM1;   // 16376

    // 1-3. gi per-gate planes (keeps GRU in the ncu-captured launch slot 4)
    for (int g = 0; g < 3; g++) {
        gemm_tn<0><<<dim3(H_ / 64, (M1 + 127) / 128), 256>>>(
            x, W_ih + (size_t)g * H_ * X_, b_ih + g * H_,
            gi + (size_t)g * B_ * T_ * H_, M1, H_, X_);
    }

    // 4. GRU scan: 8 clusters x 8 CTAs, reduce-scatter + bulk-DMA exchange
    gru_kernel<<<64, 256>>>(gi, W_hh, b_hh, hseq);

    // 5. attention + ctx
    size_t attn_smem = (size_t)(ATT_ROWS * H_ + ATT_ROWS + H_ + 8 * 132) * sizeof(float);
    cudaFuncSetAttribute(attn_kernel, cudaFuncAttributeMaxDynamicSharedMemorySize,
                         (int)attn_smem);
    attn_kernel<<<dim3(T_ / 32, B_), 256, attn_smem>>>(hseq, t, ctx);

    // 6. init head
    init_head_kernel<<<B_, 256>>>(ctx, Wi1, bi1, Wi2, bi2, m0, s0);

    // 7-9. step head MLP
    gemm_tn<1><<<dim3((H_ + 63) / 64, (M2 + 127) / 128), 256>>>(
        ctx, Ws1, bs1, hs1, M2, H_, H_ + 1);
    gemm_tn<1><<<dim3((H_ + 63) / 64, (M2 + 127) / 128), 256>>>(
        hs1, Ws2, bs2, hs2, M2, H_, H_);
    gemm_tn<0><<<dim3((3 * C_ + 63) / 64, (M2 + 127) / 128), 256>>>(
        hs2, Ws3, bs3, par, M2, 3 * C_, H_);

    // 10. OU posterior
    ou_kernel<<<32, 256>>>(par, t, eps, eps0, m0, s0, outc, part);

    // 11. finalize log_q
    finalize_q<<<1, 256>>>(part, outq);

    (void)in_sizes; (void)n_in; (void)out_size;
}